// round 16
// baseline (speedup 1.0000x reference)
#include <cuda_runtime.h>
#include <math.h>

#define Bx 256
#define Nn 1024
#define Ee 8192
#define FINc 8
#define Hh 4
#define Dd 5
#define HD 20
#define ES (Ee + Nn)          // 9216 edges incl. self loops
#define CHK (ES / 1024)       // 9 chunks of 1024 edges
#define AOUTc 64
#define OBSc 1024
#define HIDc 256
#define NOUTc 64
#define NEGs 0.2f
#define EPSbn 1e-5f
#define TOTROWS (Bx * Nn)     // 262144
#define SMEMB1 (2 * 8 * Nn * 4)   // 65536 B: sxl+sxr, 8 padded floats per node

// ---------------- device scratch ----------------
// g_h4: padded batch-major rows of 8 quads (32 floats) at r = b*Nn + n.
// head k owns quads 2k, 2k+1: padded p = k*8 + d  <->  real f = k*5 + d (d<5)
__device__ float4 g_h4[8 * TOTROWS];
__device__ float g_pool[Bx * HD];
__device__ float g_bn[4 * HD];       // [sum0(20), sq0(20), sum1(20), sq1(20)]
__device__ int   g_rowptr[Nn + 1];
__device__ int   g_cnt[CHK * Nn];
__device__ int   g_csrc[ES];
__device__ int   g_perm[Nn];         // nodes grouped by degree (warp-uniform loops)

// ---------------- helpers ----------------
__device__ __forceinline__ void edge_sd(const int* ei, int e, int& s, int& d) {
    if (e < Ee) { s = ei[e]; d = ei[Ee + e]; }
    else        { s = e - Ee; d = s; }       // appended self loops
}

// ---------------- CSR stage 1: zero + hist + rowptr scan + degree-sort perm ----------
__global__ void k_csr1(const int* __restrict__ ei) {
    __shared__ int run[Nn];
    __shared__ int sc[Nn];
    int t = threadIdx.x;
    if (t < 4 * HD) g_bn[t] = 0.f;
    run[t] = 0;
    __syncthreads();
    #pragma unroll
    for (int c = 0; c < CHK; c++) {
        g_cnt[c * Nn + t] = run[t];          // chunk-exclusive running count
        __syncthreads();
        int e = c * 1024 + t;
        int s, d; edge_sd(ei, e, s, d);
        atomicAdd(&run[d], 1);
        __syncthreads();
    }
    int tot = run[t];                        // degree of node t
    sc[t] = tot;
    __syncthreads();
    for (int off = 1; off < Nn; off <<= 1) { // Hillis-Steele inclusive scan
        int v = (t >= off) ? sc[t - off] : 0;
        __syncthreads();
        sc[t] += v;
        __syncthreads();
    }
    g_rowptr[t] = sc[t] - tot;               // exclusive
    if (t == Nn - 1) g_rowptr[Nn] = sc[t];
    __syncthreads();

    // ---- degree-sort permutation (counting sort by degree)
    int deg = tot > (Nn - 1) ? (Nn - 1) : tot;
    run[t] = 0;
    __syncthreads();
    atomicAdd(&run[deg], 1);
    __syncthreads();
    int cnt = run[t];
    sc[t] = cnt;
    __syncthreads();
    for (int off = 1; off < Nn; off <<= 1) {
        int v = (t >= off) ? sc[t - off] : 0;
        __syncthreads();
        sc[t] += v;
        __syncthreads();
    }
    run[t] = sc[t] - cnt;                    // exclusive bin offsets
    __syncthreads();
    sc[t] = 0;                               // bin cursors
    __syncthreads();
    int slot = run[deg] + atomicAdd(&sc[deg], 1);
    g_perm[slot] = t;
}

// ---------------- CSR scatter: match_any + warp-serialized cursors ----------
__global__ void k_scatter(const int* __restrict__ ei) {
    __shared__ int cur[Nn];
    int t = threadIdx.x;                      // 1024
    int chunk = blockIdx.x;                   // 9
    cur[t] = g_rowptr[t] + g_cnt[chunk * Nn + t];
    __syncthreads();
    int e = chunk * 1024 + t;
    int s, d; edge_sd(ei, e, s, d);
    int w = t >> 5, lane = t & 31;
    #pragma unroll 1
    for (int ww = 0; ww < 32; ww++) {         // warps take turns -> stable order
        if (w == ww) {
            unsigned mask = __match_any_sync(0xffffffffu, d);
            int leader = __ffs(mask) - 1;
            int rank = __popc(mask & ((1u << lane) - 1u));
            int base = 0;
            if (lane == leader) base = atomicAdd(&cur[d], __popc(mask));
            base = __shfl_sync(0xffffffffu, base, leader);
            g_csrc[base + rank] = s;
        }
        __syncthreads();
    }
}

// ---------------- GAT single-head body: block = (batch b, head k) -------------------
// sxl/sxr: node-major rows of 8 floats (2 quads, slots 5-7 = 0). Thread t: node perm[t].
// Per-thread live state ~42 regs -> spill-free below the 64-reg/1024-thread cap.
#define GAT_EDGE1(q0, q1)                                                      \
    do {                                                                       \
        float xlv[5] = {(q0).x, (q0).y, (q0).z, (q0).w, (q1).x};               \
        float e0 = 0.f;                                                        \
        _Pragma("unroll")                                                      \
        for (int d = 0; d < 5; d++) {                                          \
            float v0 = xlv[d] + xr[d];                                         \
            v0 = fmaxf(v0, NEGs * v0);                                         \
            e0 = fmaf(v0, satp[d], e0);                                        \
        }                                                                      \
        float w0 = __expf(e0);                                                 \
        s0 += w0;                                                              \
        _Pragma("unroll")                                                      \
        for (int d = 0; d < 5; d++)                                            \
            acc[d] = fmaf(w0, xlv[d], acc[d]);                                 \
    } while (0)

__device__ __forceinline__ void gat_head(
    float* sxl, float* sxr, const float* satp, const float* sbp,
    int b, int k, int slot, int doPool, int writeH) {
    int t = threadIdx.x;
    int n = g_perm[t];
    const float4* xl4 = (const float4*)sxl;
    float4* xr4 = (float4*)sxr;

    float xr[5];
    {
        float4 v0 = xr4[n * 2 + 0];
        float4 v1 = xr4[n * 2 + 1];
        xr[0] = v0.x; xr[1] = v0.y; xr[2] = v0.z; xr[3] = v0.w; xr[4] = v1.x;
    }

    float s0 = 0.f, acc[5] = {0.f, 0.f, 0.f, 0.f, 0.f};

    int beg = g_rowptr[n], end = g_rowptr[n + 1];
    int e = beg;
    for (; e + 1 < end; e += 2) {            // 2-edge pipeline: 4 quads in flight
        int sA = g_csrc[e], sB = g_csrc[e + 1];
        float4 a0 = xl4[sA * 2 + 0];
        float4 a1 = xl4[sA * 2 + 1];
        float4 b0 = xl4[sB * 2 + 0];
        float4 b1 = xl4[sB * 2 + 1];
        GAT_EDGE1(a0, a1);
        GAT_EDGE1(b0, b1);
    }
    if (e < end) {
        int sA = g_csrc[e];
        float4 a0 = xl4[sA * 2 + 0];
        float4 a1 = xl4[sA * 2 + 1];
        GAT_EDGE1(a0, a1);
    }

    float o[5];
    float inv0 = 1.f / s0;
    #pragma unroll
    for (int d = 0; d < 5; d++) o[d] = fmaf(acc[d], inv0, sbp[d]);

    float4 oq0 = make_float4(o[0], o[1], o[2], o[3]);
    float4 oq1 = make_float4(o[4], 0.f, 0.f, 0.f);

    if (writeH) {                            // layer0 only
        size_t r = (size_t)b * Nn + n;
        g_h4[r * 8 + 2 * k + 0] = oq0;
        g_h4[r * 8 + 2 * k + 1] = oq1;
    }

    // stage o into own sxr row (rows are thread-private for reads)
    xr4[n * 2 + 0] = oq0;
    xr4[n * 2 + 1] = oq1;
    __syncthreads();

    // BN stats: warp w (<5) reduces feature slot w over all 1024 nodes
    int w = t >> 5, l = t & 31;
    if (w < Dd) {
        float s1r = 0.f, s2r = 0.f;
        #pragma unroll
        for (int c = 0; c < Nn / 32; c++) {
            float v = sxr[(c * 32 + l) * 8 + w];
            s1r += v;
            s2r = fmaf(v, v, s2r);
        }
        #pragma unroll
        for (int off = 16; off; off >>= 1) {
            s1r += __shfl_down_sync(0xffffffffu, s1r, off);
            s2r += __shfl_down_sync(0xffffffffu, s2r, off);
        }
        if (l == 0) {
            int f = k * Dd + w;                        // real feature index
            atomicAdd(&g_bn[slot * 2 * HD + f],      s1r);
            atomicAdd(&g_bn[slot * 2 * HD + HD + f], s2r);
            if (doPool) g_pool[b * HD + f] = s1r * (1.f / Nn);
        }
    }
}

// ---------------- layer 0: lin0 (head k cols) -> smem -> GAT head + stats -----------
__global__ void __launch_bounds__(1024) k_layer0(
    const float* __restrict__ x,
    const float* __restrict__ Wl, const float* __restrict__ Wr,
    const float* __restrict__ att, const float* __restrict__ bias) {
    extern __shared__ float sm[];
    float* sxl = sm;                 // [1024][8]
    float* sxr = sm + 8 * Nn;
    __shared__ float swl[FINc * Dd], swr[FINc * Dd], satp[Dd], sbp[Dd];
    int t = threadIdx.x;
    int b = blockIdx.x >> 2, k = blockIdx.x & 3;

    if (t < FINc * Dd) {             // W columns for this head: o_real = k*5 + j
        int i = t / Dd, j = t % Dd;
        swl[t] = Wl[i * HD + k * Dd + j];
        swr[t] = Wr[i * HD + k * Dd + j];
    }
    if (t < Dd) {
        satp[t] = att[k * Dd + t];
        sbp[t]  = bias[k * Dd + t];
    }
    __syncthreads();

    // lin0 head-slice for node t (coalesced x read; 16B smem stores)
    {
        const float4* xp = (const float4*)(x + ((size_t)b * Nn + t) * FINc);
        float4 a0 = xp[0], a1 = xp[1];
        float xv[FINc] = {a0.x, a0.y, a0.z, a0.w, a1.x, a1.y, a1.z, a1.w};
        float al[Dd], ar[Dd];
        #pragma unroll
        for (int o = 0; o < Dd; o++) {
            float l = 0.f, r = 0.f;
            #pragma unroll
            for (int i = 0; i < FINc; i++) {
                l = fmaf(xv[i], swl[i * Dd + o], l);
                r = fmaf(xv[i], swr[i * Dd + o], r);
            }
            al[o] = l; ar[o] = r;
        }
        float4* xl4 = (float4*)sxl;
        float4* xr4 = (float4*)sxr;
        xl4[t * 2 + 0] = make_float4(al[0], al[1], al[2], al[3]);
        xl4[t * 2 + 1] = make_float4(al[4], 0.f, 0.f, 0.f);
        xr4[t * 2 + 0] = make_float4(ar[0], ar[1], ar[2], ar[3]);
        xr4[t * 2 + 1] = make_float4(ar[4], 0.f, 0.f, 0.f);
    }
    __syncthreads();

    gat_head(sxl, sxr, satp, sbp, b, k, 0, 0, 1);
}

// ---------------- layer 1: BN0 affine + lin1 (head k cols) + GAT head + stats + pool -
__global__ void __launch_bounds__(1024) k_layer1(
    const float* __restrict__ Wl, const float* __restrict__ Wr,
    const float* __restrict__ att, const float* __restrict__ bias,
    const float* __restrict__ gam, const float* __restrict__ bet) {
    extern __shared__ float sm[];
    float* sxl = sm;
    float* sxr = sm + 8 * Nn;
    __shared__ float swl[HD * Dd], swr[HD * Dd], satp[Dd], sbp[Dd], sa[HD], sc_[HD];
    int t = threadIdx.x;
    int b = blockIdx.x >> 2, k = blockIdx.x & 3;

    if (t < HD * Dd) {
        int i = t / Dd, j = t % Dd;
        swl[t] = Wl[i * HD + k * Dd + j];
        swr[t] = Wr[i * HD + k * Dd + j];
    }
    if (t < Dd) {
        satp[t] = att[k * Dd + t];
        sbp[t]  = bias[k * Dd + t];
    }
    if (t < HD) {
        float mu  = g_bn[t] * (1.f / TOTROWS);
        float var = g_bn[HD + t] * (1.f / TOTROWS) - mu * mu;
        float a = gam[t] * rsqrtf(var + EPSbn);
        sa[t] = a;
        sc_[t] = bet[t] - mu * a;
    }
    __syncthreads();

    // BN0 affine + lin1 head-slice for node t (coalesced 128B row reads)
    {
        size_t r0 = (size_t)b * Nn + t;
        float v[HD];
        #pragma unroll
        for (int kk = 0; kk < 4; kk++) {
            float4 h0 = g_h4[r0 * 8 + 2 * kk + 0];
            float4 h1 = g_h4[r0 * 8 + 2 * kk + 1];
            v[kk * Dd + 0] = h0.x; v[kk * Dd + 1] = h0.y;
            v[kk * Dd + 2] = h0.z; v[kk * Dd + 3] = h0.w;
            v[kk * Dd + 4] = h1.x;
        }
        #pragma unroll
        for (int f = 0; f < HD; f++) v[f] = fmaf(v[f], sa[f], sc_[f]);
        float al[Dd], ar[Dd];
        #pragma unroll
        for (int o = 0; o < Dd; o++) {
            float l = 0.f, r = 0.f;
            #pragma unroll
            for (int i = 0; i < HD; i++) {
                l = fmaf(v[i], swl[i * Dd + o], l);
                r = fmaf(v[i], swr[i * Dd + o], r);
            }
            al[o] = l; ar[o] = r;
        }
        float4* xl4 = (float4*)sxl;
        float4* xr4 = (float4*)sxr;
        xl4[t * 2 + 0] = make_float4(al[0], al[1], al[2], al[3]);
        xl4[t * 2 + 1] = make_float4(al[4], 0.f, 0.f, 0.f);
        xr4[t * 2 + 0] = make_float4(ar[0], ar[1], ar[2], ar[3]);
        xr4[t * 2 + 1] = make_float4(ar[4], 0.f, 0.f, 0.f);
    }
    __syncthreads();   // all g_h4 reads done before any later overwrite

    gat_head(sxl, sxr, satp, sbp, b, k, 1, 1, 0);   // no global h write needed
}

// ---------------- head: BN1-affine pool -> agg -> [agg,obs] MLP (2 rows / block) ------
__global__ void k_head(const float* __restrict__ obs,
                       const float* __restrict__ g1, const float* __restrict__ be1,
                       const float* __restrict__ Wagg, const float* __restrict__ bagg,
                       const float* __restrict__ W1, const float* __restrict__ bh1,
                       const float* __restrict__ W2, const float* __restrict__ bh2,
                       const float* __restrict__ Wout, const float* __restrict__ bout,
                       float* __restrict__ out) {
    __shared__ float f[2][AOUTc + OBSc];        // 2 x 1088
    __shared__ float h1s[2][HIDc];
    __shared__ float h2s[2][HIDc / 2];
    __shared__ float sa[HD], sc_[HD];
    int t = threadIdx.x;
    int b0 = blockIdx.x * 2;

    if (t < HD) {
        float mu  = g_bn[2 * HD + t] * (1.f / TOTROWS);
        float var = g_bn[3 * HD + t] * (1.f / TOTROWS) - mu * mu;
        float a = g1[t] * rsqrtf(var + EPSbn);
        sa[t] = a;
        sc_[t] = be1[t] - mu * a;
    }
    __syncthreads();

    if (t < AOUTc) {
        #pragma unroll
        for (int r = 0; r < 2; r++) {
            float acc = bagg[t];
            #pragma unroll
            for (int i = 0; i < HD; i++) {
                float p = fmaf(g_pool[(b0 + r) * HD + i], sa[i], sc_[i]);
                acc = fmaf(p, Wagg[i * AOUTc + t], acc);
            }
            f[r][t] = acc;
        }
    }
    #pragma unroll
    for (int r = 0; r < 2; r++)
        for (int i = t; i < OBSc; i += 256)
            f[r][AOUTc + i] = obs[(b0 + r) * OBSc + i];
    __syncthreads();

    {   // layer 1: 1088 -> 256, tanh
        float a0 = bh1[t], a1 = bh1[t];
        #pragma unroll 8
        for (int i = 0; i < AOUTc + OBSc; i++) {
            float w = W1[i * HIDc + t];
            a0 = fmaf(f[0][i], w, a0);
            a1 = fmaf(f[1][i], w, a1);
        }
        h1s[0][t] = tanhf(a0); h1s[1][t] = tanhf(a1);
    }
    __syncthreads();

    if (t < HIDc / 2) {   // layer 2: 256 -> 128, tanh
        float acc[2];
        #pragma unroll
        for (int r = 0; r < 2; r++) acc[r] = bh2[t];
        #pragma unroll 8
        for (int i = 0; i < HIDc; i++) {
            float w = W2[i * (HIDc / 2) + t];
            #pragma unroll
            for (int r = 0; r < 2; r++) acc[r] = fmaf(h1s[r][i], w, acc[r]);
        }
        #pragma unroll
        for (int r = 0; r < 2; r++) h2s[r][t] = tanhf(acc[r]);
    }
    __syncthreads();

    if (t < NOUTc) {      // out: 128 -> 64
        float acc[2];
        #pragma unroll
        for (int r = 0; r < 2; r++) acc[r] = bout[t];
        #pragma unroll 8
        for (int i = 0; i < HIDc / 2; i++) {
            float w = Wout[i * NOUTc + t];
            #pragma unroll
            for (int r = 0; r < 2; r++) acc[r] = fmaf(h2s[r][i], w, acc[r]);
        }
        #pragma unroll
        for (int r = 0; r < 2; r++) out[(b0 + r) * NOUTc + t] = acc[r];
    }
}

// ---------------- launch ----------------
extern "C" void kernel_launch(void* const* d_in, const int* in_sizes, int n_in,
                              void* d_out, int out_size) {
    const float* x    = (const float*)d_in[0];
    const float* obs  = (const float*)d_in[1];
    const int*   ei   = (const int*)  d_in[2];
    const float* Wl0  = (const float*)d_in[3];
    const float* Wr0  = (const float*)d_in[4];
    const float* att0 = (const float*)d_in[5];
    const float* b0   = (const float*)d_in[6];
    const float* Wl1  = (const float*)d_in[7];
    const float* Wr1  = (const float*)d_in[8];
    const float* att1 = (const float*)d_in[9];
    const float* b1   = (const float*)d_in[10];
    const float* g0   = (const float*)d_in[11];
    const float* be0  = (const float*)d_in[12];
    const float* g1   = (const float*)d_in[13];
    const float* be1  = (const float*)d_in[14];
    const float* Wagg = (const float*)d_in[15];
    const float* bagg = (const float*)d_in[16];
    const float* W1   = (const float*)d_in[17];
    const float* bh1  = (const float*)d_in[18];
    const float* W2   = (const float*)d_in[19];
    const float* bh2  = (const float*)d_in[20];
    const float* Wout = (const float*)d_in[21];
    const float* bout = (const float*)d_in[22];
    float* out = (float*)d_out;

    cudaFuncSetAttribute(k_layer0, cudaFuncAttributeMaxDynamicSharedMemorySize, SMEMB1);
    cudaFuncSetAttribute(k_layer1, cudaFuncAttributeMaxDynamicSharedMemorySize, SMEMB1);

    k_csr1<<<1, 1024>>>(ei);
    k_scatter<<<CHK, 1024>>>(ei);
    k_layer0<<<Bx * 4, 1024, SMEMB1>>>(x, Wl0, Wr0, att0, b0);
    k_layer1<<<Bx * 4, 1024, SMEMB1>>>(Wl1, Wr1, att1, b1, g0, be0); // <- profiled
    k_head<<<Bx / 2, 256>>>(obs, g1, be1, Wagg, bagg, W1, bh1, W2, bh2, Wout, bout, out);
}

// round 17
// speedup vs baseline: 1.3927x; 1.3927x over previous
#include <cuda_runtime.h>
#include <math.h>

#define Bx 256
#define Nn 1024
#define Ee 8192               // real edges only; self-loops handled in registers
#define FINc 8
#define Hh 4
#define Dd 5
#define HD 20
#define CHK (Ee / 1024)       // 8 chunks of 1024 edges
#define AOUTc 64
#define OBSc 1024
#define HIDc 256
#define NOUTc 64
#define NEGs 0.2f
#define EPSbn 1e-5f
#define TOTROWS (Bx * Nn)     // 262144
#define SMEMB (12 * Nn * 4)   // 49152 B: sxl only (12 padded floats per node)

// ---------------- device scratch ----------------
// g_h4: padded batch-major rows of 6 quads at r = b*Nn + n.
// pair k owns quads 3k..3k+2; padded p = k*12 + hh*6 + d <-> real f = (2k+hh)*5+d (d<5)
__device__ float4 g_h4[6 * TOTROWS];
__device__ float g_pool[Bx * HD];
__device__ float g_bn[4 * HD];       // [sum0(20), sq0(20), sum1(20), sq1(20)]
__device__ int   g_rowptr[Nn + 1];
__device__ int   g_cnt[CHK * Nn];
__device__ int   g_csrc[Ee];
__device__ int   g_perm[Nn];         // nodes grouped by degree (warp-uniform loops)

// ---------------- CSR stage 1: zero + hist + rowptr scan + degree-sort perm ----------
__global__ void k_csr1(const int* __restrict__ ei) {
    __shared__ int run[Nn];
    __shared__ int sc[Nn];
    int t = threadIdx.x;
    if (t < 4 * HD) g_bn[t] = 0.f;
    run[t] = 0;
    __syncthreads();
    #pragma unroll
    for (int c = 0; c < CHK; c++) {
        g_cnt[c * Nn + t] = run[t];          // chunk-exclusive running count
        __syncthreads();
        int e = c * 1024 + t;
        atomicAdd(&run[ei[Ee + e]], 1);      // dst
        __syncthreads();
    }
    int tot = run[t];                        // real degree of node t
    sc[t] = tot;
    __syncthreads();
    for (int off = 1; off < Nn; off <<= 1) { // Hillis-Steele inclusive scan
        int v = (t >= off) ? sc[t - off] : 0;
        __syncthreads();
        sc[t] += v;
        __syncthreads();
    }
    g_rowptr[t] = sc[t] - tot;               // exclusive
    if (t == Nn - 1) g_rowptr[Nn] = sc[t];
    __syncthreads();

    // ---- degree-sort permutation (counting sort by degree)
    int deg = tot > (Nn - 1) ? (Nn - 1) : tot;
    run[t] = 0;
    __syncthreads();
    atomicAdd(&run[deg], 1);
    __syncthreads();
    int cnt = run[t];
    sc[t] = cnt;
    __syncthreads();
    for (int off = 1; off < Nn; off <<= 1) {
        int v = (t >= off) ? sc[t - off] : 0;
        __syncthreads();
        sc[t] += v;
        __syncthreads();
    }
    run[t] = sc[t] - cnt;                    // exclusive bin offsets
    __syncthreads();
    sc[t] = 0;                               // bin cursors
    __syncthreads();
    int slot = run[deg] + atomicAdd(&sc[deg], 1);
    g_perm[slot] = t;
}

// ---------------- CSR scatter: match_any + warp-serialized cursors ----------
__global__ void k_scatter(const int* __restrict__ ei) {
    __shared__ int cur[Nn];
    int t = threadIdx.x;                      // 1024
    int chunk = blockIdx.x;                   // 8
    cur[t] = g_rowptr[t] + g_cnt[chunk * Nn + t];
    __syncthreads();
    int e = chunk * 1024 + t;
    int s = ei[e], d = ei[Ee + e];
    int w = t >> 5, lane = t & 31;
    #pragma unroll 1
    for (int ww = 0; ww < 32; ww++) {         // warps take turns -> stable order
        if (w == ww) {
            unsigned mask = __match_any_sync(0xffffffffu, d);
            int leader = __ffs(mask) - 1;
            int rank = __popc(mask & ((1u << lane) - 1u));
            int base = 0;
            if (lane == leader) base = atomicAdd(&cur[d], __popc(mask));
            base = __shfl_sync(0xffffffffu, base, leader);
            g_csrc[base + rank] = s;
        }
        __syncthreads();
    }
}

// ---------------- GAT edge math on ambient xr/satp/s0/s1/acc ----------------
#define GAT_EDGE_V(xlv)                                                        \
    do {                                                                       \
        float e0 = 0.f, e1 = 0.f;                                              \
        _Pragma("unroll")                                                      \
        for (int d = 0; d < 5; d++) {                                          \
            float v0 = (xlv)[d] + xr[d];                                       \
            v0 = fmaxf(v0, NEGs * v0);                                         \
            e0 = fmaf(v0, satp[d], e0);                                        \
            float v1 = (xlv)[6 + d] + xr[6 + d];                               \
            v1 = fmaxf(v1, NEGs * v1);                                         \
            e1 = fmaf(v1, satp[6 + d], e1);                                    \
        }                                                                      \
        float w0 = __expf(e0), w1 = __expf(e1);                                \
        s0 += w0; s1 += w1;                                                    \
        _Pragma("unroll")                                                      \
        for (int d = 0; d < 5; d++) {                                          \
            acc[d]     = fmaf(w0, (xlv)[d],     acc[d]);                       \
            acc[6 + d] = fmaf(w1, (xlv)[6 + d], acc[6 + d]);                   \
        }                                                                      \
    } while (0)

// ---------------- GAT core: self-loop from regs + CSR gather + stats ----------------
// sxl: node-major rows of 12 floats (3 quads). Thread t owns node n = perm[t]:
// its own xl (xlself) and xr live in REGISTERS; sxl is reused as output staging.
// Must be called by ALL 1024 threads (contains __syncthreads).
__device__ __forceinline__ void gat_core(
    float* sxl, const float* satp, const float* sbp,
    const float xlself[12], const float xr[12],
    int n, int b, int k, int slot, int doPool, int writeH) {
    int t = threadIdx.x;
    const float4* xl4 = (const float4*)sxl;

    float s0 = 0.f, s1 = 0.f, acc[12];
    #pragma unroll
    for (int i = 0; i < 12; i++) acc[i] = 0.f;

    GAT_EDGE_V(xlself);                      // self-loop: zero memory ops

    __syncthreads();                         // all xl rows visible in sxl

    int beg = g_rowptr[n], end = g_rowptr[n + 1];
    int e = beg;
    for (; e + 1 < end; e += 2) {            // 2-edge pipeline: 6 quads in flight
        int sA = g_csrc[e], sB = g_csrc[e + 1];
        float4 a0 = xl4[sA * 3 + 0];
        float4 a1 = xl4[sA * 3 + 1];
        float4 a2 = xl4[sA * 3 + 2];
        float4 b0 = xl4[sB * 3 + 0];
        float4 b1 = xl4[sB * 3 + 1];
        float4 b2 = xl4[sB * 3 + 2];
        float xa[12] = {a0.x, a0.y, a0.z, a0.w, a1.x, a1.y, a1.z, a1.w,
                        a2.x, a2.y, a2.z, a2.w};
        float xb[12] = {b0.x, b0.y, b0.z, b0.w, b1.x, b1.y, b1.z, b1.w,
                        b2.x, b2.y, b2.z, b2.w};
        GAT_EDGE_V(xa);
        GAT_EDGE_V(xb);
    }
    if (e < end) {
        int sA = g_csrc[e];
        float4 a0 = xl4[sA * 3 + 0];
        float4 a1 = xl4[sA * 3 + 1];
        float4 a2 = xl4[sA * 3 + 2];
        float xa[12] = {a0.x, a0.y, a0.z, a0.w, a1.x, a1.y, a1.z, a1.w,
                        a2.x, a2.y, a2.z, a2.w};
        GAT_EDGE_V(xa);
    }

    float o[12];
    float inv0 = 1.f / s0, inv1 = 1.f / s1;
    #pragma unroll
    for (int d = 0; d < 5; d++) {
        o[d]     = fmaf(acc[d],     inv0, sbp[d]);
        o[6 + d] = fmaf(acc[6 + d], inv1, sbp[6 + d]);
    }
    o[5] = 0.f; o[11] = 0.f;                 // pads exact zero

    if (writeH) {                            // layer0 only
        size_t r = (size_t)b * Nn + n;
        #pragma unroll
        for (int q = 0; q < 3; q++)
            g_h4[r * 6 + k * 3 + q] =
                make_float4(o[q*4], o[q*4+1], o[q*4+2], o[q*4+3]);
    }

    __syncthreads();                         // all gathers from sxl complete
    float4* st4 = (float4*)sxl;              // reuse sxl as output staging
    #pragma unroll
    for (int q = 0; q < 3; q++)
        st4[n * 3 + q] = make_float4(o[q*4], o[q*4+1], o[q*4+2], o[q*4+3]);
    __syncthreads();

    // BN stats: warp w (<12) reduces padded feature w over all 1024 nodes
    int w = t >> 5, l = t & 31;
    if (w < 12 && (w % 6) < Dd) {
        float s1r = 0.f, s2r = 0.f;
        #pragma unroll
        for (int c = 0; c < Nn / 32; c++) {
            float v = sxl[(c * 32 + l) * 12 + w];
            s1r += v;
            s2r = fmaf(v, v, s2r);
        }
        #pragma unroll
        for (int off = 16; off; off >>= 1) {
            s1r += __shfl_down_sync(0xffffffffu, s1r, off);
            s2r += __shfl_down_sync(0xffffffffu, s2r, off);
        }
        if (l == 0) {
            int f = k * 10 + (w / 6) * 5 + (w % 6);    // real feature index
            atomicAdd(&g_bn[slot * 2 * HD + f],      s1r);
            atomicAdd(&g_bn[slot * 2 * HD + HD + f], s2r);
            if (doPool) g_pool[b * HD + f] = s1r * (1.f / Nn);
        }
    }
}

// ---------------- layer 0: lin0 for node perm[t] -> xl smem / xr regs + GAT ---------
__global__ void __launch_bounds__(1024) k_layer0(
    const float* __restrict__ x,
    const float* __restrict__ Wl, const float* __restrict__ Wr,
    const float* __restrict__ att, const float* __restrict__ bias) {
    extern __shared__ float sm[];
    float* sxl = sm;                 // [1024][12]
    __shared__ float swl[FINc * 10], swr[FINc * 10], satp[12], sbp[12];
    int t = threadIdx.x;
    int b = blockIdx.x >> 1, k = blockIdx.x & 1;

    if (t < FINc * 10) {             // W columns for this pair: o_real = k*10 + j
        int i = t / 10, j = t % 10;
        swl[t] = Wl[i * HD + k * 10 + j];
        swr[t] = Wr[i * HD + k * 10 + j];
    }
    if (t < 12) {
        int d = t % 6;
        int f = k * 10 + (t / 6) * 5 + d;
        satp[t] = (d < Dd) ? att[f]  : 0.f;
        sbp[t]  = (d < Dd) ? bias[f] : 0.f;
    }
    __syncthreads();

    int n = g_perm[t];
    float al[12], ar[12];
    {   // lin0 for node n (scattered 32B row read; own row -> regs + smem)
        const float4* xp = (const float4*)(x + ((size_t)b * Nn + n) * FINc);
        float4 a0 = xp[0], a1 = xp[1];
        float xv[FINc] = {a0.x, a0.y, a0.z, a0.w, a1.x, a1.y, a1.z, a1.w};
        #pragma unroll
        for (int j = 0; j < 12; j++) {
            int d = j % 6;
            if (d < Dd) {
                int o = (j / 6) * 5 + d;
                float l = 0.f, r = 0.f;
                #pragma unroll
                for (int i = 0; i < FINc; i++) {
                    l = fmaf(xv[i], swl[i * 10 + o], l);
                    r = fmaf(xv[i], swr[i * 10 + o], r);
                }
                al[j] = l; ar[j] = r;
            } else { al[j] = 0.f; ar[j] = 0.f; }
        }
        float4* xl4 = (float4*)sxl;
        #pragma unroll
        for (int q = 0; q < 3; q++)
            xl4[n * 3 + q] = make_float4(al[q*4], al[q*4+1], al[q*4+2], al[q*4+3]);
    }

    gat_core(sxl, satp, sbp, al, ar, n, b, k, 0, 0, 1);
}

// ---------------- layer 1: BN0 affine + lin1 for node perm[t] + GAT + pool ----------
__global__ void __launch_bounds__(1024) k_layer1(
    const float* __restrict__ Wl, const float* __restrict__ Wr,
    const float* __restrict__ att, const float* __restrict__ bias,
    const float* __restrict__ gam, const float* __restrict__ bet) {
    extern __shared__ float sm[];
    float* sxl = sm;
    __shared__ float swl[HD * 10], swr[HD * 10], satp[12], sbp[12], sa[HD], sc_[HD];
    int t = threadIdx.x;
    int b = blockIdx.x >> 1, k = blockIdx.x & 1;

    if (t < HD * 10) {
        int i = t / 10, j = t % 10;
        swl[t] = Wl[i * HD + k * 10 + j];
        swr[t] = Wr[i * HD + k * 10 + j];
    }
    if (t < 12) {
        int d = t % 6;
        int f = k * 10 + (t / 6) * 5 + d;
        satp[t] = (d < Dd) ? att[f]  : 0.f;
        sbp[t]  = (d < Dd) ? bias[f] : 0.f;
    }
    if (t < HD) {
        float mu  = g_bn[t] * (1.f / TOTROWS);
        float var = g_bn[HD + t] * (1.f / TOTROWS) - mu * mu;
        float a = gam[t] * rsqrtf(var + EPSbn);
        sa[t] = a;
        sc_[t] = bet[t] - mu * a;
    }
    __syncthreads();

    int n = g_perm[t];
    float al[12], ar[12];
    {   // BN0 affine + lin1 for node n (scattered 96B padded-row read)
        size_t r0 = (size_t)b * Nn + n;
        float vp[24];
        #pragma unroll
        for (int q = 0; q < 6; q++) {
            float4 h4 = g_h4[r0 * 6 + q];
            vp[q*4+0] = h4.x; vp[q*4+1] = h4.y; vp[q*4+2] = h4.z; vp[q*4+3] = h4.w;
        }
        float v[HD];
        #pragma unroll
        for (int f = 0; f < HD; f++) {
            int p = (f / 10) * 12 + ((f / 5) % 2) * 6 + (f % 5);
            v[f] = fmaf(vp[p], sa[f], sc_[f]);
        }
        #pragma unroll
        for (int j = 0; j < 12; j++) {
            int d = j % 6;
            if (d < Dd) {
                int o = (j / 6) * 5 + d;
                float l = 0.f, r = 0.f;
                #pragma unroll
                for (int i = 0; i < HD; i++) {
                    l = fmaf(v[i], swl[i * 10 + o], l);
                    r = fmaf(v[i], swr[i * 10 + o], r);
                }
                al[j] = l; ar[j] = r;
            } else { al[j] = 0.f; ar[j] = 0.f; }
        }
        float4* xl4 = (float4*)sxl;
        #pragma unroll
        for (int q = 0; q < 3; q++)
            xl4[n * 3 + q] = make_float4(al[q*4], al[q*4+1], al[q*4+2], al[q*4+3]);
    }

    gat_core(sxl, satp, sbp, al, ar, n, b, k, 1, 1, 0);
}

// ---------------- head: BN1-affine pool -> agg -> [agg,obs] MLP (2 rows / block) ------
__global__ void k_head(const float* __restrict__ obs,
                       const float* __restrict__ g1, const float* __restrict__ be1,
                       const float* __restrict__ Wagg, const float* __restrict__ bagg,
                       const float* __restrict__ W1, const float* __restrict__ bh1,
                       const float* __restrict__ W2, const float* __restrict__ bh2,
                       const float* __restrict__ Wout, const float* __restrict__ bout,
                       float* __restrict__ out) {
    __shared__ float f[2][AOUTc + OBSc];        // 2 x 1088
    __shared__ float h1s[2][HIDc];
    __shared__ float h2s[2][HIDc / 2];
    __shared__ float sa[HD], sc_[HD];
    int t = threadIdx.x;
    int b0 = blockIdx.x * 2;

    if (t < HD) {
        float mu  = g_bn[2 * HD + t] * (1.f / TOTROWS);
        float var = g_bn[3 * HD + t] * (1.f / TOTROWS) - mu * mu;
        float a = g1[t] * rsqrtf(var + EPSbn);
        sa[t] = a;
        sc_[t] = be1[t] - mu * a;
    }
    __syncthreads();

    if (t < AOUTc) {
        #pragma unroll
        for (int r = 0; r < 2; r++) {
            float acc = bagg[t];
            #pragma unroll
            for (int i = 0; i < HD; i++) {
                float p = fmaf(g_pool[(b0 + r) * HD + i], sa[i], sc_[i]);
                acc = fmaf(p, Wagg[i * AOUTc + t], acc);
            }
            f[r][t] = acc;
        }
    }
    #pragma unroll
    for (int r = 0; r < 2; r++)
        for (int i = t; i < OBSc; i += 256)
            f[r][AOUTc + i] = obs[(b0 + r) * OBSc + i];
    __syncthreads();

    {   // layer 1: 1088 -> 256, tanh
        float a0 = bh1[t], a1 = bh1[t];
        #pragma unroll 8
        for (int i = 0; i < AOUTc + OBSc; i++) {
            float w = W1[i * HIDc + t];
            a0 = fmaf(f[0][i], w, a0);
            a1 = fmaf(f[1][i], w, a1);
        }
        h1s[0][t] = tanhf(a0); h1s[1][t] = tanhf(a1);
    }
    __syncthreads();

    if (t < HIDc / 2) {   // layer 2: 256 -> 128, tanh
        float acc[2];
        #pragma unroll
        for (int r = 0; r < 2; r++) acc[r] = bh2[t];
        #pragma unroll 8
        for (int i = 0; i < HIDc; i++) {
            float w = W2[i * (HIDc / 2) + t];
            #pragma unroll
            for (int r = 0; r < 2; r++) acc[r] = fmaf(h1s[r][i], w, acc[r]);
        }
        #pragma unroll
        for (int r = 0; r < 2; r++) h2s[r][t] = tanhf(acc[r]);
    }
    __syncthreads();

    if (t < NOUTc) {      // out: 128 -> 64
        float acc[2];
        #pragma unroll
        for (int r = 0; r < 2; r++) acc[r] = bout[t];
        #pragma unroll 8
        for (int i = 0; i < HIDc / 2; i++) {
            float w = Wout[i * NOUTc + t];
            #pragma unroll
            for (int r = 0; r < 2; r++) acc[r] = fmaf(h2s[r][i], w, acc[r]);
        }
        #pragma unroll
        for (int r = 0; r < 2; r++) out[(b0 + r) * NOUTc + t] = acc[r];
    }
}

// ---------------- launch ----------------
extern "C" void kernel_launch(void* const* d_in, const int* in_sizes, int n_in,
                              void* d_out, int out_size) {
    const float* x    = (const float*)d_in[0];
    const float* obs  = (const float*)d_in[1];
    const int*   ei   = (const int*)  d_in[2];
    const float* Wl0  = (const float*)d_in[3];
    const float* Wr0  = (const float*)d_in[4];
    const float* att0 = (const float*)d_in[5];
    const float* b0   = (const float*)d_in[6];
    const float* Wl1  = (const float*)d_in[7];
    const float* Wr1  = (const float*)d_in[8];
    const float* att1 = (const float*)d_in[9];
    const float* b1   = (const float*)d_in[10];
    const float* g0   = (const float*)d_in[11];
    const float* be0  = (const float*)d_in[12];
    const float* g1   = (const float*)d_in[13];
    const float* be1  = (const float*)d_in[14];
    const float* Wagg = (const float*)d_in[15];
    const float* bagg = (const float*)d_in[16];
    const float* W1   = (const float*)d_in[17];
    const float* bh1  = (const float*)d_in[18];
    const float* W2   = (const float*)d_in[19];
    const float* bh2  = (const float*)d_in[20];
    const float* Wout = (const float*)d_in[21];
    const float* bout = (const float*)d_in[22];
    float* out = (float*)d_out;

    cudaFuncSetAttribute(k_layer0, cudaFuncAttributeMaxDynamicSharedMemorySize, SMEMB);
    cudaFuncSetAttribute(k_layer1, cudaFuncAttributeMaxDynamicSharedMemorySize, SMEMB);

    k_csr1<<<1, 1024>>>(ei);
    k_scatter<<<CHK, 1024>>>(ei);
    k_layer0<<<Bx * 2, 1024, SMEMB>>>(x, Wl0, Wr0, att0, b0);
    k_layer1<<<Bx * 2, 1024, SMEMB>>>(Wl1, Wr1, att1, b1, g0, be0); // <- profiled
    k_head<<<Bx / 2, 256>>>(obs, g1, be1, Wagg, bagg, W1, bh1, W2, bh2, Wout, bout, out);
}